// round 12
// baseline (speedup 1.0000x reference)
#include <cuda_runtime.h>
#include <cuda_fp16.h>
#include <cstdint>

#define BATCH 8
#define CIN 3
#define HW 320
#define HW2 (HW*HW)
#define PS 10
#define P2 100
#define P2P 112
#define NPATCH 1024
#define IMGS 16

// scratch (device globals — no runtime allocation)
__device__ float g_ini[IMGS*HW2];
__device__ float g_fea[IMGS*HW2];
__device__ uint32_t g_Mh[104*56];                // (W2@W1) fp16x2, [p][k/2], padded 104x112
__device__ float g_Wc[486];                      // composed 9x9 conv: [((ci*9+uy)*9+ux)*2+c]
__device__ float g_Wp[2646];                     // per-tap composed 7x7: [((t*2+c)*3+ci)*49+s]
__device__ float g_s2[18];                       // [c*9+t] = w2[t]·b1
__device__ float g_B[2];                         // full bias
__device__ __half g_UI[(size_t)IMGS*NPATCH*P2P]; // fp16, K padded to 112
__device__ __half g_UF[(size_t)IMGS*NPATCH*P2P];

// ---------------- helpers ----------------
__device__ __forceinline__ void mma_f16(float* d, const uint32_t* a, const uint32_t* b) {
    asm volatile(
        "mma.sync.aligned.m16n8k16.row.col.f32.f16.f16.f32 "
        "{%0,%1,%2,%3}, {%4,%5,%6,%7}, {%8,%9}, {%0,%1,%2,%3};"
        : "+f"(d[0]), "+f"(d[1]), "+f"(d[2]), "+f"(d[3])
        : "r"(a[0]), "r"(a[1]), "r"(a[2]), "r"(a[3]), "r"(b[0]), "r"(b[1]));
}
__device__ __forceinline__ void ldsm4(uint32_t& r0, uint32_t& r1, uint32_t& r2, uint32_t& r3,
                                      uint32_t saddr) {
    asm volatile("ldmatrix.sync.aligned.m8n8.x4.shared.b16 {%0,%1,%2,%3}, [%4];"
                 : "=r"(r0), "=r"(r1), "=r"(r2), "=r"(r3) : "r"(saddr));
}
__device__ __forceinline__ void ldsm2(uint32_t& r0, uint32_t& r1, uint32_t saddr) {
    asm volatile("ldmatrix.sync.aligned.m8n8.x2.shared.b16 {%0,%1}, [%2];"
                 : "=r"(r0), "=r"(r1) : "r"(saddr));
}

// ---------------- M = w_lin2 @ w_lin1, fp16 padded [104][112] ----------------
__global__ void k_buildM(const float* __restrict__ w1, const float* __restrict__ w2) {
    int p = blockIdx.x;          // 0..103
    int t = threadIdx.x;         // 0..63
    if (t >= 56) return;
    int k0 = 2*t, k1 = 2*t + 1;
    float a0 = 0.f, a1 = 0.f;
    if (p < P2) {
        for (int q = 0; q < 2*P2; ++q) {
            float wq = w2[p*2*P2 + q];
            if (k0 < P2) a0 += wq * w1[q*P2 + k0];
            if (k1 < P2) a1 += wq * w1[q*P2 + k1];
        }
    }
    __half2 h = __floats2half2_rn(a0, a1);
    g_Mh[p*56 + t] = *(uint32_t*)&h;
}

// ---------------- compose conv2 o conv1 -> 9x9 kernel + per-tap 7x7 + bias terms ----------------
__global__ void k_compose(const float* __restrict__ w1, const float* __restrict__ b1,
                          const float* __restrict__ w2, const float* __restrict__ b2) {
    int idx = blockIdx.x*256 + threadIdx.x;
    if (idx < 486) {
        int c = idx / 243; int r = idx - c*243;
        int ci = r / 81; int r2 = r - ci*81;
        int uy = r2 / 9, ux = r2 - (r2/9)*9;
        float acc = 0.f;
        for (int ty = 0; ty < 3; ++ty) {
            int sy = uy - ty; if (sy < 0 || sy > 6) continue;
            for (int tx = 0; tx < 3; ++tx) {
                int sx = ux - tx; if (sx < 0 || sx > 6) continue;
                for (int m = 0; m < 64; ++m)
                    acc += w2[((c*64 + m)*3 + ty)*3 + tx] * w1[((m*3 + ci)*7 + sy)*7 + sx];
            }
        }
        g_Wc[((ci*9 + uy)*9 + ux)*2 + c] = acc;
    } else if (idx < 486 + 2646) {
        int j = idx - 486;
        int t = j / 294; int r = j - t*294;
        int c = r / 147; int r2 = r - c*147;
        int ci = r2 / 49; int s = r2 - ci*49;
        int ty = t / 3, tx = t - ty*3;
        int sy = s / 7, sx = s - sy*7;
        float acc = 0.f;
        for (int m = 0; m < 64; ++m)
            acc += w2[((c*64 + m)*3 + ty)*3 + tx] * w1[((m*3 + ci)*7 + sy)*7 + sx];
        g_Wp[j] = acc;
    } else if (idx < 486 + 2646 + 18) {
        int j = idx - 3132;
        int c = j / 9, t = j - (j/9)*9;
        int ty = t / 3, tx = t - ty*3;
        float acc = 0.f;
        for (int m = 0; m < 64; ++m)
            acc += w2[((c*64 + m)*3 + ty)*3 + tx] * b1[m];
        g_s2[j] = acc;
    } else if (idx < 486 + 2646 + 18 + 2) {
        int c = idx - 3150;
        float acc = b2[c];
        for (int t = 0; t < 9; ++t) {
            int ty = t / 3, tx = t - ty*3;
            float s = 0.f;
            for (int m = 0; m < 64; ++m)
                s += w2[((c*64 + m)*3 + ty)*3 + tx] * b1[m];
            acc += s;
        }
        g_B[c] = acc;
    }
}

// ---------------- ini = composed 9x9 conv (3->2) + exact border-ring fixup ----------------
__global__ __launch_bounds__(256) void k_ini(const float* __restrict__ x) {
    __shared__ float sx[3*40*40];
    __shared__ float sWc[486];
    __shared__ float sWp[2646];
    __shared__ float sS[18];
    __shared__ float sB[2];
    int tid = threadIdx.x;
    int img = blockIdx.z;
    int oy0 = blockIdx.y*32, ox0 = blockIdx.x*32;

    const float* xb = x + (size_t)img*CIN*HW2;
    for (int idx = tid; idx < 4800; idx += 256) {
        int ci = idx / 1600; int r = idx - ci*1600;
        int iy = r / 40, ix = r - iy*40;
        int gy = oy0 - 4 + iy, gx = ox0 - 4 + ix;
        float v = 0.f;
        if (gy >= 0 && gy < HW && gx >= 0 && gx < HW)
            v = xb[ci*HW2 + gy*HW + gx];
        sx[idx] = v;
    }
    for (int idx = tid; idx < 486; idx += 256) sWc[idx] = g_Wc[idx];
    for (int idx = tid; idx < 2646; idx += 256) sWp[idx] = g_Wp[idx];
    if (tid < 18) sS[tid] = g_s2[tid];
    if (tid < 2) sB[tid] = g_B[tid];
    __syncthreads();

    int row = tid >> 3;
    int xq = (tid & 7) * 4;
    float acc0[4], acc1[4];
    #pragma unroll
    for (int dx = 0; dx < 4; ++dx) { acc0[dx] = sB[0]; acc1[dx] = sB[1]; }

    #pragma unroll 1
    for (int ci = 0; ci < 3; ++ci) {
        #pragma unroll
        for (int uy = 0; uy < 9; ++uy) {
            const float* rp = &sx[ci*1600 + (row + uy)*40 + xq];
            float4 v0 = *(const float4*)rp;
            float4 v1 = *(const float4*)(rp + 4);
            float4 v2 = *(const float4*)(rp + 8);
            float vv[12] = {v0.x, v0.y, v0.z, v0.w, v1.x, v1.y, v1.z, v1.w,
                            v2.x, v2.y, v2.z, v2.w};
            const float2* wp = (const float2*)&sWc[(ci*9 + uy)*9*2];
            #pragma unroll
            for (int ux = 0; ux < 9; ++ux) {
                float2 w = wp[ux];
                #pragma unroll
                for (int dx = 0; dx < 4; ++dx) {
                    acc0[dx] += vv[ux + dx] * w.x;
                    acc1[dx] += vv[ux + dx] * w.y;
                }
            }
        }
    }

    int y = oy0 + row;
    bool edge_tile = (oy0 == 0) | (oy0 == HW - 32) | (ox0 == 0) | (ox0 == HW - 32);
    if (edge_tile) {
        #pragma unroll 1
        for (int dx = 0; dx < 4; ++dx) {
            int xg = ox0 + xq + dx;
            if (y != 0 && y != HW-1 && xg != 0 && xg != HW-1) continue;
            for (int t = 0; t < 9; ++t) {
                int ty = t / 3, tx = t - ty*3;
                int py = y + ty - 1, px = xg + tx - 1;
                if (py >= 0 && py < HW && px >= 0 && px < HW) continue;
                acc0[dx] -= sS[t];
                acc1[dx] -= sS[9 + t];
                for (int ci = 0; ci < 3; ++ci)
                    for (int sy = 0; sy < 7; ++sy)
                        for (int sx7 = 0; sx7 < 7; ++sx7) {
                            float v = sx[ci*1600 + (row + ty + sy)*40 + (xq + dx + tx + sx7)];
                            acc0[dx] -= v * sWp[((t*2 + 0)*3 + ci)*49 + sy*7 + sx7];
                            acc1[dx] -= v * sWp[((t*2 + 1)*3 + ci)*49 + sy*7 + sx7];
                        }
            }
        }
    }

    size_t ob = ((size_t)img*2)*HW2 + (size_t)y*HW + ox0 + xq;
    *(float4*)&g_ini[ob]       = make_float4(acc0[0], acc0[1], acc0[2], acc0[3]);
    *(float4*)&g_ini[ob + HW2] = make_float4(acc1[0], acc1[1], acc1[2], acc1[3]);
}

// ---------------- fea: 1x1 conv 3->2, /4, vectorized ----------------
__global__ __launch_bounds__(256) void k_fea(const float* __restrict__ x,
        const float* __restrict__ wfm, const float* __restrict__ bfm) {
    int idx = blockIdx.x*256 + threadIdx.x;
    int img = idx / (HW2/4);
    int p4 = (idx - img*(HW2/4)) * 4;
    const float* xb = x + (size_t)img*CIN*HW2 + p4;
    float4 x0 = *(const float4*)xb;
    float4 x1 = *(const float4*)(xb + HW2);
    float4 x2 = *(const float4*)(xb + 2*HW2);
    #pragma unroll
    for (int c = 0; c < 2; ++c) {
        float f0 = wfm[c*3+0], f1 = wfm[c*3+1], f2 = wfm[c*3+2], fb = bfm[c];
        float4 o;
        o.x = (x0.x*f0 + x1.x*f1 + x2.x*f2 + fb)*0.25f;
        o.y = (x0.y*f0 + x1.y*f1 + x2.y*f2 + fb)*0.25f;
        o.z = (x0.z*f0 + x1.z*f1 + x2.z*f2 + fb)*0.25f;
        o.w = (x0.w*f0 + x1.w*f1 + x2.w*f2 + fb)*0.25f;
        *(float4*)(g_fea + ((size_t)img*2 + c)*HW2 + p4) = o;
    }
}

// ---------------- trans: relu(M @ v) per patch, fp16 mma + ldmatrix ----------------
#define TRS 60               // uint32 stride (120 halves); 60 mod 32 = 28 -> ldmatrix conflict-free
#define TR_SMEM ((104*TRS + 128*TRS)*4)

template<int J0, int NJ>
__device__ __forceinline__ void trans_warp(uint32_t sMb, uint32_t sAb,
                                           __half* db, int m0, int lane) {
    constexpr int NP = NJ/2;
    int g = lane >> 3, l7 = lane & 7;
    int ac = lane & 3, lq = lane >> 2;

    uint32_t a_base[2];
    #pragma unroll
    for (int i = 0; i < 2; ++i) {
        int rowr = m0 + 16*i + l7 + (g & 1)*8;
        a_base[i] = sAb + (uint32_t)(rowr*TRS + (g >> 1)*4)*4;
    }
    uint32_t b_base[NP > 0 ? NP : 1];
    #pragma unroll
    for (int jp = 0; jp < NP; ++jp) {
        int rowr = 8*(J0 + 2*jp) + 8*(g >> 1) + l7;
        b_base[jp] = sMb + (uint32_t)(rowr*TRS + (g & 1)*4)*4;
    }
    uint32_t b1b = 0;
    if (NJ & 1) {
        int rowr = 8*(J0 + NJ - 1) + l7;
        b1b = sMb + (uint32_t)(rowr*TRS + ((lane >> 3) & 1)*4)*4;
    }

    float d[2][NJ][4];
    #pragma unroll
    for (int i = 0; i < 2; ++i)
        #pragma unroll
        for (int j = 0; j < NJ; ++j)
            #pragma unroll
            for (int q = 0; q < 4; ++q) d[i][j][q] = 0.f;

    #pragma unroll
    for (int kc = 0; kc < 7; ++kc) {
        uint32_t ko = kc*32;
        uint32_t a[2][4], bf[NJ][2];
        #pragma unroll
        for (int i = 0; i < 2; ++i)
            ldsm4(a[i][0], a[i][1], a[i][2], a[i][3], a_base[i] + ko);
        #pragma unroll
        for (int jp = 0; jp < NP; ++jp)
            ldsm4(bf[2*jp][0], bf[2*jp][1], bf[2*jp+1][0], bf[2*jp+1][1], b_base[jp] + ko);
        if (NJ & 1)
            ldsm2(bf[NJ-1][0], bf[NJ-1][1], b1b + ko);
        #pragma unroll
        for (int i = 0; i < 2; ++i)
            #pragma unroll
            for (int j = 0; j < NJ; ++j)
                mma_f16(d[i][j], a[i], bf[j]);
    }

    #pragma unroll
    for (int i = 0; i < 2; ++i) {
        #pragma unroll
        for (int rr = 0; rr < 2; ++rr) {
            int row = m0 + 16*i + lq + 8*rr;
            #pragma unroll
            for (int j = 0; j < NJ; ++j) {
                int col = 8*(J0 + j) + 2*ac;
                __half2 hv = __floats2half2_rn(fmaxf(d[i][j][2*rr + 0], 0.f),
                                               fmaxf(d[i][j][2*rr + 1], 0.f));
                *(uint32_t*)&db[(size_t)row*P2P + col] = *(uint32_t*)&hv;
            }
        }
    }
}

__global__ __launch_bounds__(256) void k_trans() {
    extern __shared__ uint32_t smt[];
    uint32_t* uM = smt;                  // 104 x 60 (fp16x2)
    uint32_t* uA = smt + 104*TRS;        // 128 x 60
    int tid = threadIdx.x;
    int img = blockIdx.y;
    int l0 = blockIdx.x * 128;
    const float* src = (blockIdx.z == 0) ? g_ini : g_fea;
    __half* dst = (blockIdx.z == 0) ? g_UI : g_UF;

    for (int idx = tid; idx < 104*TRS; idx += 256) {
        int p = idx / TRS, ku = idx - p*TRS;
        uM[p*TRS + ku] = (ku < 56) ? g_Mh[p*56 + ku] : 0u;
    }
    const float* sb = src + img*HW2;
    for (int idx = tid; idx < 128*TRS; idx += 256) {
        int pi = idx / TRS, ku = idx - pi*TRS;
        float v0 = 0.f, v1 = 0.f;
        int k0 = 2*ku;
        if (k0 < P2) {
            int l = l0 + pi;
            int base = ((l >> 5)*PS)*HW + (l & 31)*PS;
            int py = k0 / PS, px = k0 - py*PS;
            v0 = sb[base + py*HW + px];
            int k1 = k0 + 1;
            if (k1 < P2) {
                int py1 = k1 / PS, px1 = k1 - py1*PS;
                v1 = sb[base + py1*HW + px1];
            }
        }
        __half2 h = __floats2half2_rn(v0, v1);
        uA[pi*TRS + ku] = *(uint32_t*)&h;
    }
    __syncthreads();

    int wid = tid >> 5, lane = tid & 31;
    int m0 = (wid & 3) * 32;
    __half* db = dst + (size_t)img*NPATCH*P2P + (size_t)l0*P2P;
    // zero K-pad cols 104..111
    {
        uint32_t* d32 = (uint32_t*)db;
        for (int idx = tid; idx < 128*4; idx += 256)
            d32[(idx >> 2)*56 + 52 + (idx & 3)] = 0u;
    }
    uint32_t sMb = (uint32_t)__cvta_generic_to_shared(uM);
    uint32_t sAb = (uint32_t)__cvta_generic_to_shared(uA);
    if (wid < 4) trans_warp<0, 7>(sMb, sAb, db, m0, lane);
    else         trans_warp<7, 6>(sMb, sAb, db, m0, lane);
}

// ---------------- att: batched 1024x1024x112 NT-GEMM, fp16 mma + ldmatrix, /100 ----------------
#define AT_STR 68            // uint32 stride; 68 mod 32 == 4 -> conflict-free
#define ATT_SMEM (2*128*AT_STR*4)
__global__ __launch_bounds__(256) void k_att(float* __restrict__ out) {
    extern __shared__ uint32_t sma[];
    uint32_t* sA = sma;
    uint32_t* sB = sma + 128*AT_STR;
    int tid = threadIdx.x;
    int wid = tid >> 5, lane = tid & 31;
    int img = blockIdx.z;
    int gl0 = blockIdx.y*128, gm0 = blockIdx.x*128;
    const __half* UI = g_UI + (size_t)img*NPATCH*P2P;
    const __half* UF = g_UF + (size_t)img*NPATCH*P2P;

    for (int it = tid; it < 128*14; it += 256) {
        int rr = it/14, c = it - rr*14;
        uint4 va = *(const uint4*)&UI[(size_t)(gl0 + rr)*P2P + c*8];
        *(uint4*)&sA[rr*AT_STR + c*4] = va;
        uint4 vb = *(const uint4*)&UF[(size_t)(gm0 + rr)*P2P + c*8];
        *(uint4*)&sB[rr*AT_STR + c*4] = vb;
    }
    __syncthreads();

    int m0 = (wid & 3)*32, n0 = (wid >> 2)*64;
    int g = lane >> 3, l7 = lane & 7;
    int ac = lane & 3, lq = lane >> 2;

    uint32_t sAb = (uint32_t)__cvta_generic_to_shared(sA);
    uint32_t sBb = (uint32_t)__cvta_generic_to_shared(sB);
    uint32_t a_base[2], b_base[4];
    #pragma unroll
    for (int i = 0; i < 2; ++i) {
        int rowr = m0 + 16*i + l7 + (g & 1)*8;
        a_base[i] = sAb + (uint32_t)(rowr*AT_STR + (g >> 1)*4)*4;
    }
    #pragma unroll
    for (int jp = 0; jp < 4; ++jp) {
        int rowr = n0 + 16*jp + 8*(g >> 1) + l7;
        b_base[jp] = sBb + (uint32_t)(rowr*AT_STR + (g & 1)*4)*4;
    }

    float d[2][8][4];
    #pragma unroll
    for (int i = 0; i < 2; ++i)
        #pragma unroll
        for (int j = 0; j < 8; ++j)
            #pragma unroll
            for (int q = 0; q < 4; ++q) d[i][j][q] = 0.f;

    #pragma unroll
    for (int kc = 0; kc < 7; ++kc) {
        uint32_t ko = kc*32;
        uint32_t a[2][4], bf[8][2];
        #pragma unroll
        for (int i = 0; i < 2; ++i)
            ldsm4(a[i][0], a[i][1], a[i][2], a[i][3], a_base[i] + ko);
        #pragma unroll
        for (int jp = 0; jp < 4; ++jp)
            ldsm4(bf[2*jp][0], bf[2*jp][1], bf[2*jp+1][0], bf[2*jp+1][1], b_base[jp] + ko);
        #pragma unroll
        for (int i = 0; i < 2; ++i)
            #pragma unroll
            for (int j = 0; j < 8; ++j)
                mma_f16(d[i][j], a[i], bf[j]);
    }

    #pragma unroll
    for (int i = 0; i < 2; ++i) {
        #pragma unroll
        for (int rr = 0; rr < 2; ++rr) {
            int l = gl0 + m0 + 16*i + lq + 8*rr;
            #pragma unroll
            for (int j = 0; j < 8; ++j) {
                int m = gm0 + n0 + 8*j + 2*ac;
                float2 v = make_float2(d[i][j][2*rr + 0]*0.01f, d[i][j][2*rr + 1]*0.01f);
                *(float2*)&out[((long)img*NPATCH + l)*NPATCH + m] = v;
            }
        }
    }
}

extern "C" void kernel_launch(void* const* d_in, const int* in_sizes, int n_in,
                              void* d_out, int out_size) {
    const float* x   = (const float*)d_in[0];
    const float* w1c = (const float*)d_in[1];
    const float* b1c = (const float*)d_in[2];
    const float* w2c = (const float*)d_in[3];
    const float* b2c = (const float*)d_in[4];
    const float* wfm = (const float*)d_in[5];
    const float* bfm = (const float*)d_in[6];
    const float* wl1 = (const float*)d_in[7];
    const float* wl2 = (const float*)d_in[8];
    float* out = (float*)d_out;

    static bool attr_set = false;
    if (!attr_set) {
        cudaFuncSetAttribute(k_trans, cudaFuncAttributeMaxDynamicSharedMemorySize, TR_SMEM);
        cudaFuncSetAttribute(k_att,   cudaFuncAttributeMaxDynamicSharedMemorySize, ATT_SMEM);
        attr_set = true;
    }

    k_buildM<<<104, 64>>>(wl1, wl2);
    k_compose<<<13, 256>>>(w1c, b1c, w2c, b2c);
    k_ini<<<dim3(10,10,BATCH), 256>>>(x);
    k_fea<<<800, 256>>>(x, wfm, bfm);
    k_trans<<<dim3(8, IMGS, 2), 256, TR_SMEM>>>();
    k_att<<<dim3(8,8,IMGS), 256, ATT_SMEM>>>(out);
}

// round 13
// speedup vs baseline: 1.0944x; 1.0944x over previous
#include <cuda_runtime.h>
#include <cuda_fp16.h>
#include <cstdint>

#define BATCH 8
#define CIN 3
#define HW 320
#define HW2 (HW*HW)
#define PS 10
#define P2 100
#define P2P 112
#define NPATCH 1024
#define IMGS 16

// scratch (device globals — no runtime allocation)
__device__ float g_ini[IMGS*HW2];
__device__ uint32_t g_Mh[104*56];                // (W2@W1) fp16x2, [p][k/2], padded 104x112
__device__ float g_Wc[486];                      // composed 9x9 conv: [((ci*9+uy)*9+ux)*2+c]
__device__ float g_Wp[2646];                     // per-tap composed 7x7: [((t*2+c)*3+ci)*49+s]
__device__ float g_s2[18];                       // [c*9+t] = w2[t]·b1
__device__ float g_B[2];                         // full bias
__device__ __half g_UI[(size_t)IMGS*NPATCH*P2P]; // fp16, K padded to 112
__device__ __half g_UF[(size_t)IMGS*NPATCH*P2P];

// ---------------- helpers ----------------
__device__ __forceinline__ void mma_f16(float* d, const uint32_t* a, const uint32_t* b) {
    asm volatile(
        "mma.sync.aligned.m16n8k16.row.col.f32.f16.f16.f32 "
        "{%0,%1,%2,%3}, {%4,%5,%6,%7}, {%8,%9}, {%0,%1,%2,%3};"
        : "+f"(d[0]), "+f"(d[1]), "+f"(d[2]), "+f"(d[3])
        : "r"(a[0]), "r"(a[1]), "r"(a[2]), "r"(a[3]), "r"(b[0]), "r"(b[1]));
}
__device__ __forceinline__ void ldsm4(uint32_t& r0, uint32_t& r1, uint32_t& r2, uint32_t& r3,
                                      uint32_t saddr) {
    asm volatile("ldmatrix.sync.aligned.m8n8.x4.shared.b16 {%0,%1,%2,%3}, [%4];"
                 : "=r"(r0), "=r"(r1), "=r"(r2), "=r"(r3) : "r"(saddr));
}
__device__ __forceinline__ void ldsm2(uint32_t& r0, uint32_t& r1, uint32_t saddr) {
    asm volatile("ldmatrix.sync.aligned.m8n8.x2.shared.b16 {%0,%1}, [%2];"
                 : "=r"(r0), "=r"(r1) : "r"(saddr));
}

// ---------------- prep: buildM (fp16) + compose conv2∘conv1, one launch ----------------
__global__ void k_prep(const float* __restrict__ wl1, const float* __restrict__ wl2,
                       const float* __restrict__ w1, const float* __restrict__ b1,
                       const float* __restrict__ w2, const float* __restrict__ b2) {
    int idx = blockIdx.x*256 + threadIdx.x;
    if (idx < 5824) {
        // M = wl2 @ wl1, fp16x2 padded [104][56]
        int p = idx / 56, t = idx - (idx/56)*56;
        int k0 = 2*t, k1 = 2*t + 1;
        float a0 = 0.f, a1 = 0.f;
        if (p < P2) {
            for (int q = 0; q < 2*P2; ++q) {
                float wq = wl2[p*2*P2 + q];
                if (k0 < P2) a0 += wq * wl1[q*P2 + k0];
                if (k1 < P2) a1 += wq * wl1[q*P2 + k1];
            }
        }
        __half2 h = __floats2half2_rn(a0, a1);
        g_Mh[p*56 + t] = *(uint32_t*)&h;
        return;
    }
    idx -= 5824;
    if (idx < 486) {
        int c = idx / 243; int r = idx - c*243;
        int ci = r / 81; int r2 = r - ci*81;
        int uy = r2 / 9, ux = r2 - (r2/9)*9;
        float acc = 0.f;
        for (int ty = 0; ty < 3; ++ty) {
            int sy = uy - ty; if (sy < 0 || sy > 6) continue;
            for (int tx = 0; tx < 3; ++tx) {
                int sx = ux - tx; if (sx < 0 || sx > 6) continue;
                for (int m = 0; m < 64; ++m)
                    acc += w2[((c*64 + m)*3 + ty)*3 + tx] * w1[((m*3 + ci)*7 + sy)*7 + sx];
            }
        }
        g_Wc[((ci*9 + uy)*9 + ux)*2 + c] = acc;
    } else if (idx < 486 + 2646) {
        int j = idx - 486;
        int t = j / 294; int r = j - t*294;
        int c = r / 147; int r2 = r - c*147;
        int ci = r2 / 49; int s = r2 - ci*49;
        int ty = t / 3, tx = t - ty*3;
        int sy = s / 7, sx = s - sy*7;
        float acc = 0.f;
        for (int m = 0; m < 64; ++m)
            acc += w2[((c*64 + m)*3 + ty)*3 + tx] * w1[((m*3 + ci)*7 + sy)*7 + sx];
        g_Wp[j] = acc;
    } else if (idx < 486 + 2646 + 18) {
        int j = idx - 3132;
        int c = j / 9, t = j - (j/9)*9;
        int ty = t / 3, tx = t - ty*3;
        float acc = 0.f;
        for (int m = 0; m < 64; ++m)
            acc += w2[((c*64 + m)*3 + ty)*3 + tx] * b1[m];
        g_s2[j] = acc;
    } else if (idx < 486 + 2646 + 18 + 2) {
        int c = idx - 3150;
        float acc = b2[c];
        for (int t = 0; t < 9; ++t) {
            int ty = t / 3, tx = t - ty*3;
            float s = 0.f;
            for (int m = 0; m < 64; ++m)
                s += w2[((c*64 + m)*3 + ty)*3 + tx] * b1[m];
            acc += s;
        }
        g_B[c] = acc;
    }
}

// ---------------- ini = composed 9x9 conv (3->2) + exact border-ring fixup ----------------
__global__ __launch_bounds__(256) void k_ini(const float* __restrict__ x) {
    __shared__ float sx[3*40*40];
    __shared__ float sWc[486];
    __shared__ float sWp[2646];
    __shared__ float sS[18];
    __shared__ float sB[2];
    int tid = threadIdx.x;
    int img = blockIdx.z;
    int oy0 = blockIdx.y*32, ox0 = blockIdx.x*32;

    const float* xb = x + (size_t)img*CIN*HW2;
    for (int idx = tid; idx < 4800; idx += 256) {
        int ci = idx / 1600; int r = idx - ci*1600;
        int iy = r / 40, ix = r - iy*40;
        int gy = oy0 - 4 + iy, gx = ox0 - 4 + ix;
        float v = 0.f;
        if (gy >= 0 && gy < HW && gx >= 0 && gx < HW)
            v = xb[ci*HW2 + gy*HW + gx];
        sx[idx] = v;
    }
    for (int idx = tid; idx < 486; idx += 256) sWc[idx] = g_Wc[idx];
    for (int idx = tid; idx < 2646; idx += 256) sWp[idx] = g_Wp[idx];
    if (tid < 18) sS[tid] = g_s2[tid];
    if (tid < 2) sB[tid] = g_B[tid];
    __syncthreads();

    int row = tid >> 3;
    int xq = (tid & 7) * 4;
    float acc0[4], acc1[4];
    #pragma unroll
    for (int dx = 0; dx < 4; ++dx) { acc0[dx] = sB[0]; acc1[dx] = sB[1]; }

    #pragma unroll 1
    for (int ci = 0; ci < 3; ++ci) {
        #pragma unroll
        for (int uy = 0; uy < 9; ++uy) {
            const float* rp = &sx[ci*1600 + (row + uy)*40 + xq];
            float4 v0 = *(const float4*)rp;
            float4 v1 = *(const float4*)(rp + 4);
            float4 v2 = *(const float4*)(rp + 8);
            float vv[12] = {v0.x, v0.y, v0.z, v0.w, v1.x, v1.y, v1.z, v1.w,
                            v2.x, v2.y, v2.z, v2.w};
            const float2* wp = (const float2*)&sWc[(ci*9 + uy)*9*2];
            #pragma unroll
            for (int ux = 0; ux < 9; ++ux) {
                float2 w = wp[ux];
                #pragma unroll
                for (int dx = 0; dx < 4; ++dx) {
                    acc0[dx] += vv[ux + dx] * w.x;
                    acc1[dx] += vv[ux + dx] * w.y;
                }
            }
        }
    }

    int y = oy0 + row;
    bool edge_tile = (oy0 == 0) | (oy0 == HW - 32) | (ox0 == 0) | (ox0 == HW - 32);
    if (edge_tile) {
        #pragma unroll 1
        for (int dx = 0; dx < 4; ++dx) {
            int xg = ox0 + xq + dx;
            if (y != 0 && y != HW-1 && xg != 0 && xg != HW-1) continue;
            for (int t = 0; t < 9; ++t) {
                int ty = t / 3, tx = t - ty*3;
                int py = y + ty - 1, px = xg + tx - 1;
                if (py >= 0 && py < HW && px >= 0 && px < HW) continue;
                acc0[dx] -= sS[t];
                acc1[dx] -= sS[9 + t];
                for (int ci = 0; ci < 3; ++ci)
                    for (int sy = 0; sy < 7; ++sy)
                        for (int sx7 = 0; sx7 < 7; ++sx7) {
                            float v = sx[ci*1600 + (row + ty + sy)*40 + (xq + dx + tx + sx7)];
                            acc0[dx] -= v * sWp[((t*2 + 0)*3 + ci)*49 + sy*7 + sx7];
                            acc1[dx] -= v * sWp[((t*2 + 1)*3 + ci)*49 + sy*7 + sx7];
                        }
            }
        }
    }

    size_t ob = ((size_t)img*2)*HW2 + (size_t)y*HW + ox0 + xq;
    *(float4*)&g_ini[ob]       = make_float4(acc0[0], acc0[1], acc0[2], acc0[3]);
    *(float4*)&g_ini[ob + HW2] = make_float4(acc1[0], acc1[1], acc1[2], acc1[3]);
}

// ---------------- trans: relu(M @ v), fp16 mma + ldmatrix; z==1 computes fea inline ----------------
#define TRS 60               // uint32 stride (120 halves)
#define TR_SMEM ((104*TRS + 128*TRS)*4)

template<int J0, int NJ>
__device__ __forceinline__ void trans_warp(uint32_t sMb, uint32_t sAb,
                                           __half* db, int m0, int lane) {
    constexpr int NP = NJ/2;
    int g = lane >> 3, l7 = lane & 7;
    int ac = lane & 3, lq = lane >> 2;

    uint32_t a_base[2];
    #pragma unroll
    for (int i = 0; i < 2; ++i) {
        int rowr = m0 + 16*i + l7 + (g & 1)*8;
        a_base[i] = sAb + (uint32_t)(rowr*TRS + (g >> 1)*4)*4;
    }
    uint32_t b_base[NP > 0 ? NP : 1];
    #pragma unroll
    for (int jp = 0; jp < NP; ++jp) {
        int rowr = 8*(J0 + 2*jp) + 8*(g >> 1) + l7;
        b_base[jp] = sMb + (uint32_t)(rowr*TRS + (g & 1)*4)*4;
    }
    uint32_t b1b = 0;
    if (NJ & 1) {
        int rowr = 8*(J0 + NJ - 1) + l7;
        b1b = sMb + (uint32_t)(rowr*TRS + ((lane >> 3) & 1)*4)*4;
    }

    float d[2][NJ][4];
    #pragma unroll
    for (int i = 0; i < 2; ++i)
        #pragma unroll
        for (int j = 0; j < NJ; ++j)
            #pragma unroll
            for (int q = 0; q < 4; ++q) d[i][j][q] = 0.f;

    #pragma unroll
    for (int kc = 0; kc < 7; ++kc) {
        uint32_t ko = kc*32;
        uint32_t a[2][4], bf[NJ][2];
        #pragma unroll
        for (int i = 0; i < 2; ++i)
            ldsm4(a[i][0], a[i][1], a[i][2], a[i][3], a_base[i] + ko);
        #pragma unroll
        for (int jp = 0; jp < NP; ++jp)
            ldsm4(bf[2*jp][0], bf[2*jp][1], bf[2*jp+1][0], bf[2*jp+1][1], b_base[jp] + ko);
        if (NJ & 1)
            ldsm2(bf[NJ-1][0], bf[NJ-1][1], b1b + ko);
        #pragma unroll
        for (int i = 0; i < 2; ++i)
            #pragma unroll
            for (int j = 0; j < NJ; ++j)
                mma_f16(d[i][j], a[i], bf[j]);
    }

    #pragma unroll
    for (int i = 0; i < 2; ++i) {
        #pragma unroll
        for (int rr = 0; rr < 2; ++rr) {
            int row = m0 + 16*i + lq + 8*rr;
            #pragma unroll
            for (int j = 0; j < NJ; ++j) {
                int col = 8*(J0 + j) + 2*ac;
                __half2 hv = __floats2half2_rn(fmaxf(d[i][j][2*rr + 0], 0.f),
                                               fmaxf(d[i][j][2*rr + 1], 0.f));
                *(uint32_t*)&db[(size_t)row*P2P + col] = *(uint32_t*)&hv;
            }
        }
    }
}

__global__ __launch_bounds__(256) void k_trans(const float* __restrict__ x,
        const float* __restrict__ wfm, const float* __restrict__ bfm) {
    extern __shared__ uint32_t smt[];
    uint32_t* uM = smt;                  // 104 x 60 (fp16x2)
    uint32_t* uA = smt + 104*TRS;        // 128 x 60
    int tid = threadIdx.x;
    int img = blockIdx.y;
    int l0 = blockIdx.x * 128;
    int fz = blockIdx.z;
    __half* dst = (fz == 0) ? g_UI : g_UF;

    for (int idx = tid; idx < 104*TRS; idx += 256) {
        int p = idx / TRS, ku = idx - p*TRS;
        uM[p*TRS + ku] = (ku < 56) ? g_Mh[p*56 + ku] : 0u;
    }

    // gather source: z==0 -> g_ini[img]; z==1 -> fea computed from x inline
    const float* sb = g_ini + (size_t)img*HW2;
    int b = img >> 1, c = img & 1;
    const float* xb0 = x + (size_t)b*CIN*HW2;
    float f0 = wfm[c*3+0], f1 = wfm[c*3+1], f2 = wfm[c*3+2], fb = bfm[c];

    for (int idx = tid; idx < 128*TRS; idx += 256) {
        int pi = idx / TRS, ku = idx - pi*TRS;
        float v0 = 0.f, v1 = 0.f;
        int k0 = 2*ku;
        if (k0 < P2) {
            int l = l0 + pi;
            int py = k0 / PS, px = k0 - py*PS;
            int off = ((l >> 5)*PS + py)*HW + (l & 31)*PS + px;
            if (fz == 0) {
                float2 a = *(const float2*)(sb + off);
                v0 = a.x; v1 = a.y;
            } else {
                float2 a0 = *(const float2*)(xb0 + off);
                float2 a1 = *(const float2*)(xb0 + HW2 + off);
                float2 a2 = *(const float2*)(xb0 + 2*HW2 + off);
                v0 = (a0.x*f0 + a1.x*f1 + a2.x*f2 + fb)*0.25f;
                v1 = (a0.y*f0 + a1.y*f1 + a2.y*f2 + fb)*0.25f;
            }
        }
        __half2 h = __floats2half2_rn(v0, v1);
        uA[pi*TRS + ku] = *(uint32_t*)&h;
    }
    __syncthreads();

    int wid = tid >> 5, lane = tid & 31;
    int m0 = (wid & 3) * 32;
    __half* db = dst + (size_t)img*NPATCH*P2P + (size_t)l0*P2P;
    // zero K-pad cols 104..111
    {
        uint32_t* d32 = (uint32_t*)db;
        for (int idx = tid; idx < 128*4; idx += 256)
            d32[(idx >> 2)*56 + 52 + (idx & 3)] = 0u;
    }
    uint32_t sMb = (uint32_t)__cvta_generic_to_shared(uM);
    uint32_t sAb = (uint32_t)__cvta_generic_to_shared(uA);
    if (wid < 4) trans_warp<0, 7>(sMb, sAb, db, m0, lane);
    else         trans_warp<7, 6>(sMb, sAb, db, m0, lane);
}

// ---------------- att: batched 1024x1024x112 NT-GEMM, fp16 mma + ldmatrix, /100 ----------------
#define AT_STR 68
#define ATT_SMEM (2*128*AT_STR*4)
__global__ __launch_bounds__(256) void k_att(float* __restrict__ out) {
    extern __shared__ uint32_t sma[];
    uint32_t* sA = sma;
    uint32_t* sB = sma + 128*AT_STR;
    int tid = threadIdx.x;
    int wid = tid >> 5, lane = tid & 31;
    int img = blockIdx.z;
    int gl0 = blockIdx.y*128, gm0 = blockIdx.x*128;
    const __half* UI = g_UI + (size_t)img*NPATCH*P2P;
    const __half* UF = g_UF + (size_t)img*NPATCH*P2P;

    for (int it = tid; it < 128*14; it += 256) {
        int rr = it/14, c = it - rr*14;
        uint4 va = *(const uint4*)&UI[(size_t)(gl0 + rr)*P2P + c*8];
        *(uint4*)&sA[rr*AT_STR + c*4] = va;
        uint4 vb = *(const uint4*)&UF[(size_t)(gm0 + rr)*P2P + c*8];
        *(uint4*)&sB[rr*AT_STR + c*4] = vb;
    }
    __syncthreads();

    int m0 = (wid & 3)*32, n0 = (wid >> 2)*64;
    int g = lane >> 3, l7 = lane & 7;
    int ac = lane & 3, lq = lane >> 2;

    uint32_t sAb = (uint32_t)__cvta_generic_to_shared(sA);
    uint32_t sBb = (uint32_t)__cvta_generic_to_shared(sB);
    uint32_t a_base[2], b_base[4];
    #pragma unroll
    for (int i = 0; i < 2; ++i) {
        int rowr = m0 + 16*i + l7 + (g & 1)*8;
        a_base[i] = sAb + (uint32_t)(rowr*AT_STR + (g >> 1)*4)*4;
    }
    #pragma unroll
    for (int jp = 0; jp < 4; ++jp) {
        int rowr = n0 + 16*jp + 8*(g >> 1) + l7;
        b_base[jp] = sBb + (uint32_t)(rowr*AT_STR + (g & 1)*4)*4;
    }

    float d[2][8][4];
    #pragma unroll
    for (int i = 0; i < 2; ++i)
        #pragma unroll
        for (int j = 0; j < 8; ++j)
            #pragma unroll
            for (int q = 0; q < 4; ++q) d[i][j][q] = 0.f;

    #pragma unroll
    for (int kc = 0; kc < 7; ++kc) {
        uint32_t ko = kc*32;
        uint32_t a[2][4], bf[8][2];
        #pragma unroll
        for (int i = 0; i < 2; ++i)
            ldsm4(a[i][0], a[i][1], a[i][2], a[i][3], a_base[i] + ko);
        #pragma unroll
        for (int jp = 0; jp < 4; ++jp)
            ldsm4(bf[2*jp][0], bf[2*jp][1], bf[2*jp+1][0], bf[2*jp+1][1], b_base[jp] + ko);
        #pragma unroll
        for (int i = 0; i < 2; ++i)
            #pragma unroll
            for (int j = 0; j < 8; ++j)
                mma_f16(d[i][j], a[i], bf[j]);
    }

    #pragma unroll
    for (int i = 0; i < 2; ++i) {
        #pragma unroll
        for (int rr = 0; rr < 2; ++rr) {
            int l = gl0 + m0 + 16*i + lq + 8*rr;
            #pragma unroll
            for (int j = 0; j < 8; ++j) {
                int m = gm0 + n0 + 8*j + 2*ac;
                float2 v = make_float2(d[i][j][2*rr + 0]*0.01f, d[i][j][2*rr + 1]*0.01f);
                *(float2*)&out[((long)img*NPATCH + l)*NPATCH + m] = v;
            }
        }
    }
}

extern "C" void kernel_launch(void* const* d_in, const int* in_sizes, int n_in,
                              void* d_out, int out_size) {
    const float* x   = (const float*)d_in[0];
    const float* w1c = (const float*)d_in[1];
    const float* b1c = (const float*)d_in[2];
    const float* w2c = (const float*)d_in[3];
    const float* b2c = (const float*)d_in[4];
    const float* wfm = (const float*)d_in[5];
    const float* bfm = (const float*)d_in[6];
    const float* wl1 = (const float*)d_in[7];
    const float* wl2 = (const float*)d_in[8];
    float* out = (float*)d_out;

    static bool attr_set = false;
    if (!attr_set) {
        cudaFuncSetAttribute(k_trans, cudaFuncAttributeMaxDynamicSharedMemorySize, TR_SMEM);
        cudaFuncSetAttribute(k_att,   cudaFuncAttributeMaxDynamicSharedMemorySize, ATT_SMEM);
        attr_set = true;
    }

    k_prep<<<36, 256>>>(wl1, wl2, w1c, b1c, w2c, b2c);
    k_ini<<<dim3(10,10,BATCH), 256>>>(x);
    k_trans<<<dim3(8, IMGS, 2), 256, TR_SMEM>>>(x, wfm, bfm);
    k_att<<<dim3(8,8,IMGS), 256, ATT_SMEM>>>(out);
}

// round 14
// speedup vs baseline: 1.0969x; 1.0023x over previous
#include <cuda_runtime.h>
#include <cuda_fp16.h>
#include <cstdint>

#define BATCH 8
#define CIN 3
#define HW 320
#define HW2 (HW*HW)
#define PS 10
#define P2 100
#define P2P 112
#define NPATCH 1024
#define IMGS 16

// scratch (device globals — no runtime allocation)
__device__ float g_ini[IMGS*HW2];
__device__ uint32_t g_Mh[104*56];                // (W2@W1) fp16x2, [p][k/2], padded 104x112
__device__ float g_Wc[486];                      // composed 9x9 conv: [((ci*9+uy)*9+ux)*2+c]
__device__ float g_Wp[2646];                     // per-tap composed 7x7: [((t*2+c)*3+ci)*49+s]
__device__ float g_s2[18];                       // [c*9+t] = w2[t]·b1
__device__ float g_B[2];                         // full bias
__device__ __half g_UI[(size_t)IMGS*NPATCH*P2P]; // fp16, K padded to 112
__device__ __half g_UF[(size_t)IMGS*NPATCH*P2P];

// ---------------- helpers ----------------
__device__ __forceinline__ void mma_f16(float* d, const uint32_t* a, const uint32_t* b) {
    asm volatile(
        "mma.sync.aligned.m16n8k16.row.col.f32.f16.f16.f32 "
        "{%0,%1,%2,%3}, {%4,%5,%6,%7}, {%8,%9}, {%0,%1,%2,%3};"
        : "+f"(d[0]), "+f"(d[1]), "+f"(d[2]), "+f"(d[3])
        : "r"(a[0]), "r"(a[1]), "r"(a[2]), "r"(a[3]), "r"(b[0]), "r"(b[1]));
}
__device__ __forceinline__ void ldsm4(uint32_t& r0, uint32_t& r1, uint32_t& r2, uint32_t& r3,
                                      uint32_t saddr) {
    asm volatile("ldmatrix.sync.aligned.m8n8.x4.shared.b16 {%0,%1,%2,%3}, [%4];"
                 : "=r"(r0), "=r"(r1), "=r"(r2), "=r"(r3) : "r"(saddr));
}
__device__ __forceinline__ void ldsm2(uint32_t& r0, uint32_t& r1, uint32_t saddr) {
    asm volatile("ldmatrix.sync.aligned.m8n8.x2.shared.b16 {%0,%1}, [%2];"
                 : "=r"(r0), "=r"(r1) : "r"(saddr));
}

// ---------------- prep: buildM (fp16) + compose conv2∘conv1, one launch ----------------
__global__ void k_prep(const float* __restrict__ wl1, const float* __restrict__ wl2,
                       const float* __restrict__ w1, const float* __restrict__ b1,
                       const float* __restrict__ w2, const float* __restrict__ b2) {
    int idx = blockIdx.x*256 + threadIdx.x;
    if (idx < 5824) {
        int p = idx / 56, t = idx - (idx/56)*56;
        int k0 = 2*t, k1 = 2*t + 1;
        float a0 = 0.f, a1 = 0.f;
        if (p < P2) {
            for (int q = 0; q < 2*P2; ++q) {
                float wq = wl2[p*2*P2 + q];
                if (k0 < P2) a0 += wq * wl1[q*P2 + k0];
                if (k1 < P2) a1 += wq * wl1[q*P2 + k1];
            }
        }
        __half2 h = __floats2half2_rn(a0, a1);
        g_Mh[p*56 + t] = *(uint32_t*)&h;
        return;
    }
    idx -= 5824;
    if (idx < 486) {
        int c = idx / 243; int r = idx - c*243;
        int ci = r / 81; int r2 = r - ci*81;
        int uy = r2 / 9, ux = r2 - (r2/9)*9;
        float acc = 0.f;
        for (int ty = 0; ty < 3; ++ty) {
            int sy = uy - ty; if (sy < 0 || sy > 6) continue;
            for (int tx = 0; tx < 3; ++tx) {
                int sx = ux - tx; if (sx < 0 || sx > 6) continue;
                for (int m = 0; m < 64; ++m)
                    acc += w2[((c*64 + m)*3 + ty)*3 + tx] * w1[((m*3 + ci)*7 + sy)*7 + sx];
            }
        }
        g_Wc[((ci*9 + uy)*9 + ux)*2 + c] = acc;
    } else if (idx < 486 + 2646) {
        int j = idx - 486;
        int t = j / 294; int r = j - t*294;
        int c = r / 147; int r2 = r - c*147;
        int ci = r2 / 49; int s = r2 - ci*49;
        int ty = t / 3, tx = t - ty*3;
        int sy = s / 7, sx = s - sy*7;
        float acc = 0.f;
        for (int m = 0; m < 64; ++m)
            acc += w2[((c*64 + m)*3 + ty)*3 + tx] * w1[((m*3 + ci)*7 + sy)*7 + sx];
        g_Wp[j] = acc;
    } else if (idx < 486 + 2646 + 18) {
        int j = idx - 3132;
        int c = j / 9, t = j - (j/9)*9;
        int ty = t / 3, tx = t - ty*3;
        float acc = 0.f;
        for (int m = 0; m < 64; ++m)
            acc += w2[((c*64 + m)*3 + ty)*3 + tx] * b1[m];
        g_s2[j] = acc;
    } else if (idx < 486 + 2646 + 18 + 2) {
        int c = idx - 3150;
        float acc = b2[c];
        for (int t = 0; t < 9; ++t) {
            int ty = t / 3, tx = t - ty*3;
            float s = 0.f;
            for (int m = 0; m < 64; ++m)
                s += w2[((c*64 + m)*3 + ty)*3 + tx] * b1[m];
            acc += s;
        }
        g_B[c] = acc;
    }
}

// ---------------- ini = composed 9x9 conv (3->2) + exact border-ring fixup ----------------
__global__ __launch_bounds__(256) void k_ini(const float* __restrict__ x) {
    __shared__ float sx[3*40*40];
    __shared__ float sWc[486];
    __shared__ float sWp[2646];
    __shared__ float sS[18];
    __shared__ float sB[2];
    int tid = threadIdx.x;
    int img = blockIdx.z;
    int oy0 = blockIdx.y*32, ox0 = blockIdx.x*32;

    const float* xb = x + (size_t)img*CIN*HW2;
    for (int idx = tid; idx < 4800; idx += 256) {
        int ci = idx / 1600; int r = idx - ci*1600;
        int iy = r / 40, ix = r - iy*40;
        int gy = oy0 - 4 + iy, gx = ox0 - 4 + ix;
        float v = 0.f;
        if (gy >= 0 && gy < HW && gx >= 0 && gx < HW)
            v = xb[ci*HW2 + gy*HW + gx];
        sx[idx] = v;
    }
    for (int idx = tid; idx < 486; idx += 256) sWc[idx] = g_Wc[idx];
    for (int idx = tid; idx < 2646; idx += 256) sWp[idx] = g_Wp[idx];
    if (tid < 18) sS[tid] = g_s2[tid];
    if (tid < 2) sB[tid] = g_B[tid];
    __syncthreads();

    int row = tid >> 3;
    int xq = (tid & 7) * 4;
    float acc0[4], acc1[4];
    #pragma unroll
    for (int dx = 0; dx < 4; ++dx) { acc0[dx] = sB[0]; acc1[dx] = sB[1]; }

    #pragma unroll 1
    for (int ci = 0; ci < 3; ++ci) {
        #pragma unroll
        for (int uy = 0; uy < 9; ++uy) {
            const float* rp = &sx[ci*1600 + (row + uy)*40 + xq];
            float4 v0 = *(const float4*)rp;
            float4 v1 = *(const float4*)(rp + 4);
            float4 v2 = *(const float4*)(rp + 8);
            float vv[12] = {v0.x, v0.y, v0.z, v0.w, v1.x, v1.y, v1.z, v1.w,
                            v2.x, v2.y, v2.z, v2.w};
            const float2* wp = (const float2*)&sWc[(ci*9 + uy)*9*2];
            #pragma unroll
            for (int ux = 0; ux < 9; ++ux) {
                float2 w = wp[ux];
                #pragma unroll
                for (int dx = 0; dx < 4; ++dx) {
                    acc0[dx] += vv[ux + dx] * w.x;
                    acc1[dx] += vv[ux + dx] * w.y;
                }
            }
        }
    }

    int y = oy0 + row;
    bool edge_tile = (oy0 == 0) | (oy0 == HW - 32) | (ox0 == 0) | (ox0 == HW - 32);
    if (edge_tile) {
        #pragma unroll 1
        for (int dx = 0; dx < 4; ++dx) {
            int xg = ox0 + xq + dx;
            if (y != 0 && y != HW-1 && xg != 0 && xg != HW-1) continue;
            for (int t = 0; t < 9; ++t) {
                int ty = t / 3, tx = t - ty*3;
                int py = y + ty - 1, px = xg + tx - 1;
                if (py >= 0 && py < HW && px >= 0 && px < HW) continue;
                acc0[dx] -= sS[t];
                acc1[dx] -= sS[9 + t];
                for (int ci = 0; ci < 3; ++ci)
                    for (int sy = 0; sy < 7; ++sy)
                        for (int sx7 = 0; sx7 < 7; ++sx7) {
                            float v = sx[ci*1600 + (row + ty + sy)*40 + (xq + dx + tx + sx7)];
                            acc0[dx] -= v * sWp[((t*2 + 0)*3 + ci)*49 + sy*7 + sx7];
                            acc1[dx] -= v * sWp[((t*2 + 1)*3 + ci)*49 + sy*7 + sx7];
                        }
            }
        }
    }

    size_t ob = ((size_t)img*2)*HW2 + (size_t)y*HW + ox0 + xq;
    *(float4*)&g_ini[ob]       = make_float4(acc0[0], acc0[1], acc0[2], acc0[3]);
    *(float4*)&g_ini[ob + HW2] = make_float4(acc1[0], acc1[1], acc1[2], acc1[3]);
}

// ---------------- trans: relu(M @ v), fp16 mma + ldmatrix; tile M=64, 128 thr ----------------
#define TRS 60               // uint32 stride (120 halves)
#define TR_SMEM ((104*TRS + 64*TRS)*4)

template<int J0, int NJ>
__device__ __forceinline__ void trans_warp(uint32_t sMb, uint32_t sAb,
                                           __half* db, int m0, int lane) {
    constexpr int NP = NJ/2;
    int g = lane >> 3, l7 = lane & 7;
    int ac = lane & 3, lq = lane >> 2;

    uint32_t a_base[2];
    #pragma unroll
    for (int i = 0; i < 2; ++i) {
        int rowr = m0 + 16*i + l7 + (g & 1)*8;
        a_base[i] = sAb + (uint32_t)(rowr*TRS + (g >> 1)*4)*4;
    }
    uint32_t b_base[NP > 0 ? NP : 1];
    #pragma unroll
    for (int jp = 0; jp < NP; ++jp) {
        int rowr = 8*(J0 + 2*jp) + 8*(g >> 1) + l7;
        b_base[jp] = sMb + (uint32_t)(rowr*TRS + (g & 1)*4)*4;
    }
    uint32_t b1b = 0;
    if (NJ & 1) {
        int rowr = 8*(J0 + NJ - 1) + l7;
        b1b = sMb + (uint32_t)(rowr*TRS + ((lane >> 3) & 1)*4)*4;
    }

    float d[2][NJ][4];
    #pragma unroll
    for (int i = 0; i < 2; ++i)
        #pragma unroll
        for (int j = 0; j < NJ; ++j)
            #pragma unroll
            for (int q = 0; q < 4; ++q) d[i][j][q] = 0.f;

    #pragma unroll
    for (int kc = 0; kc < 7; ++kc) {
        uint32_t ko = kc*32;
        uint32_t a[2][4], bf[NJ][2];
        #pragma unroll
        for (int i = 0; i < 2; ++i)
            ldsm4(a[i][0], a[i][1], a[i][2], a[i][3], a_base[i] + ko);
        #pragma unroll
        for (int jp = 0; jp < NP; ++jp)
            ldsm4(bf[2*jp][0], bf[2*jp][1], bf[2*jp+1][0], bf[2*jp+1][1], b_base[jp] + ko);
        if (NJ & 1)
            ldsm2(bf[NJ-1][0], bf[NJ-1][1], b1b + ko);
        #pragma unroll
        for (int i = 0; i < 2; ++i)
            #pragma unroll
            for (int j = 0; j < NJ; ++j)
                mma_f16(d[i][j], a[i], bf[j]);
    }

    #pragma unroll
    for (int i = 0; i < 2; ++i) {
        #pragma unroll
        for (int rr = 0; rr < 2; ++rr) {
            int row = m0 + 16*i + lq + 8*rr;
            #pragma unroll
            for (int j = 0; j < NJ; ++j) {
                int col = 8*(J0 + j) + 2*ac;
                __half2 hv = __floats2half2_rn(fmaxf(d[i][j][2*rr + 0], 0.f),
                                               fmaxf(d[i][j][2*rr + 1], 0.f));
                *(uint32_t*)&db[(size_t)row*P2P + col] = *(uint32_t*)&hv;
            }
        }
    }
}

__global__ __launch_bounds__(128) void k_trans(const float* __restrict__ x,
        const float* __restrict__ wfm, const float* __restrict__ bfm) {
    extern __shared__ uint32_t smt[];
    uint32_t* uM = smt;                  // 104 x 60 (fp16x2)
    uint32_t* uA = smt + 104*TRS;        // 64 x 60
    int tid = threadIdx.x;
    int img = blockIdx.y;
    int l0 = blockIdx.x * 64;
    int fz = blockIdx.z;
    __half* dst = (fz == 0) ? g_UI : g_UF;

    for (int idx = tid; idx < 104*TRS; idx += 128) {
        int p = idx / TRS, ku = idx - p*TRS;
        uM[p*TRS + ku] = (ku < 56) ? g_Mh[p*56 + ku] : 0u;
    }

    const float* sb = g_ini + (size_t)img*HW2;
    int b = img >> 1, c = img & 1;
    const float* xb0 = x + (size_t)b*CIN*HW2;
    float f0 = wfm[c*3+0], f1 = wfm[c*3+1], f2 = wfm[c*3+2], fb = bfm[c];

    for (int idx = tid; idx < 64*TRS; idx += 128) {
        int pi = idx / TRS, ku = idx - pi*TRS;
        float v0 = 0.f, v1 = 0.f;
        int k0 = 2*ku;
        if (k0 < P2) {
            int l = l0 + pi;
            int py = k0 / PS, px = k0 - py*PS;
            int off = ((l >> 5)*PS + py)*HW + (l & 31)*PS + px;
            if (fz == 0) {
                float2 a = *(const float2*)(sb + off);
                v0 = a.x; v1 = a.y;
            } else {
                float2 a0 = *(const float2*)(xb0 + off);
                float2 a1 = *(const float2*)(xb0 + HW2 + off);
                float2 a2 = *(const float2*)(xb0 + 2*HW2 + off);
                v0 = (a0.x*f0 + a1.x*f1 + a2.x*f2 + fb)*0.25f;
                v1 = (a0.y*f0 + a1.y*f1 + a2.y*f2 + fb)*0.25f;
            }
        }
        __half2 h = __floats2half2_rn(v0, v1);
        uA[pi*TRS + ku] = *(uint32_t*)&h;
    }
    __syncthreads();

    int wid = tid >> 5, lane = tid & 31;
    int m0 = (wid & 1) * 32;
    __half* db = dst + (size_t)img*NPATCH*P2P + (size_t)l0*P2P;
    // zero K-pad cols 104..111 (64 rows x 4 uint32)
    {
        uint32_t* d32 = (uint32_t*)db;
        for (int idx = tid; idx < 64*4; idx += 128)
            d32[(idx >> 2)*56 + 52 + (idx & 3)] = 0u;
    }
    uint32_t sMb = (uint32_t)__cvta_generic_to_shared(uM);
    uint32_t sAb = (uint32_t)__cvta_generic_to_shared(uA);
    if (wid < 2) trans_warp<0, 7>(sMb, sAb, db, m0, lane);
    else         trans_warp<7, 6>(sMb, sAb, db, m0, lane);
}

// ---------------- att: 1024x1024x112 NT-GEMM, fp16 mma + ldmatrix; tile 64x128, 128 thr ----------------
#define AT_STR 68
#define ATT_SMEM ((64 + 128)*AT_STR*4)
__global__ __launch_bounds__(128) void k_att(float* __restrict__ out) {
    extern __shared__ uint32_t sma[];
    uint32_t* sA = sma;                  // 64 rows
    uint32_t* sB = sma + 64*AT_STR;      // 128 rows
    int tid = threadIdx.x;
    int wid = tid >> 5, lane = tid & 31;
    int img = blockIdx.z;
    int gl0 = blockIdx.y*64, gm0 = blockIdx.x*128;
    const __half* UI = g_UI + (size_t)img*NPATCH*P2P;
    const __half* UF = g_UF + (size_t)img*NPATCH*P2P;

    for (int it = tid; it < 192*14; it += 128) {
        int rr = it/14, c = it - rr*14;
        if (rr < 64) {
            uint4 va = *(const uint4*)&UI[(size_t)(gl0 + rr)*P2P + c*8];
            *(uint4*)&sA[rr*AT_STR + c*4] = va;
        } else {
            uint4 vb = *(const uint4*)&UF[(size_t)(gm0 + rr - 64)*P2P + c*8];
            *(uint4*)&sB[(rr - 64)*AT_STR + c*4] = vb;
        }
    }
    __syncthreads();

    int m0 = (wid & 1)*32, n0 = (wid >> 1)*64;
    int g = lane >> 3, l7 = lane & 7;
    int ac = lane & 3, lq = lane >> 2;

    uint32_t sAb = (uint32_t)__cvta_generic_to_shared(sA);
    uint32_t sBb = (uint32_t)__cvta_generic_to_shared(sB);
    uint32_t a_base[2], b_base[4];
    #pragma unroll
    for (int i = 0; i < 2; ++i) {
        int rowr = m0 + 16*i + l7 + (g & 1)*8;
        a_base[i] = sAb + (uint32_t)(rowr*AT_STR + (g >> 1)*4)*4;
    }
    #pragma unroll
    for (int jp = 0; jp < 4; ++jp) {
        int rowr = n0 + 16*jp + 8*(g >> 1) + l7;
        b_base[jp] = sBb + (uint32_t)(rowr*AT_STR + (g & 1)*4)*4;
    }

    float d[2][8][4];
    #pragma unroll
    for (int i = 0; i < 2; ++i)
        #pragma unroll
        for (int j = 0; j < 8; ++j)
            #pragma unroll
            for (int q = 0; q < 4; ++q) d[i][j][q] = 0.f;

    #pragma unroll
    for (int kc = 0; kc < 7; ++kc) {
        uint32_t ko = kc*32;
        uint32_t a[2][4], bf[8][2];
        #pragma unroll
        for (int i = 0; i < 2; ++i)
            ldsm4(a[i][0], a[i][1], a[i][2], a[i][3], a_base[i] + ko);
        #pragma unroll
        for (int jp = 0; jp < 4; ++jp)
            ldsm4(bf[2*jp][0], bf[2*jp][1], bf[2*jp+1][0], bf[2*jp+1][1], b_base[jp] + ko);
        #pragma unroll
        for (int i = 0; i < 2; ++i)
            #pragma unroll
            for (int j = 0; j < 8; ++j)
                mma_f16(d[i][j], a[i], bf[j]);
    }

    #pragma unroll
    for (int i = 0; i < 2; ++i) {
        #pragma unroll
        for (int rr = 0; rr < 2; ++rr) {
            int l = gl0 + m0 + 16*i + lq + 8*rr;
            #pragma unroll
            for (int j = 0; j < 8; ++j) {
                int m = gm0 + n0 + 8*j + 2*ac;
                float2 v = make_float2(d[i][j][2*rr + 0]*0.01f, d[i][j][2*rr + 1]*0.01f);
                *(float2*)&out[((long)img*NPATCH + l)*NPATCH + m] = v;
            }
        }
    }
}

extern "C" void kernel_launch(void* const* d_in, const int* in_sizes, int n_in,
                              void* d_out, int out_size) {
    const float* x   = (const float*)d_in[0];
    const float* w1c = (const float*)d_in[1];
    const float* b1c = (const float*)d_in[2];
    const float* w2c = (const float*)d_in[3];
    const float* b2c = (const float*)d_in[4];
    const float* wfm = (const float*)d_in[5];
    const float* bfm = (const float*)d_in[6];
    const float* wl1 = (const float*)d_in[7];
    const float* wl2 = (const float*)d_in[8];
    float* out = (float*)d_out;

    static bool attr_set = false;
    if (!attr_set) {
        cudaFuncSetAttribute(k_trans, cudaFuncAttributeMaxDynamicSharedMemorySize, TR_SMEM);
        cudaFuncSetAttribute(k_att,   cudaFuncAttributeMaxDynamicSharedMemorySize, ATT_SMEM);
        attr_set = true;
    }

    k_prep<<<36, 256>>>(wl1, wl2, w1c, b1c, w2c, b2c);
    k_ini<<<dim3(10,10,BATCH), 256>>>(x);
    k_trans<<<dim3(16, IMGS, 2), 128, TR_SMEM>>>(x, wfm, bfm);
    k_att<<<dim3(8,16,IMGS), 128, ATT_SMEM>>>(out);
}